// round 3
// baseline (speedup 1.0000x reference)
#include <cuda_runtime.h>

// ---------------- problem constants ----------------
#define N_TOK   16384
#define DIM     1024
#define HEADS   8
#define DHEAD   64
#define HD      (HEADS * DHEAD)   // 512
#define QKVW    (3 * HD)          // 1536
#define WSZ     128
#define NWIN    (N_TOK / WSZ)     // 128

// ---------------- scratch (static device arrays; no allocs allowed) ----------------
__device__ float g_qkv[(size_t)N_TOK * QKVW];   // ~100.7 MB
__device__ float g_attn[(size_t)N_TOK * HD];    // ~33.6 MB

// ---------------- SGEMM: C[M,N] = A[M,K] @ B[K,N] (+bias), all row-major ----------------
// 128x128 block tile, BK=16, 8x8 per thread, 256 threads. M,N,K all multiples of tile dims.
#define BM 128
#define BN 128
#define BK 16
#define TM 8
#define TN 8

template <bool WITH_BIAS>
__global__ __launch_bounds__(256, 2)
void sgemm128(const float* __restrict__ A, const float* __restrict__ B,
              const float* __restrict__ bias, float* __restrict__ C,
              int M, int N, int K)
{
    __shared__ float As[BK][BM];
    __shared__ float Bs[BK][BN];

    const int tid  = threadIdx.x;
    const int row0 = blockIdx.y * BM;
    const int col0 = blockIdx.x * BN;

    // global->smem load mapping
    const int aRow = tid >> 2;          // 0..63  (+64 second pass)
    const int aCol = (tid & 3) * 4;     // 0,4,8,12
    const int bRow = tid >> 5;          // 0..7   (+8 second pass)
    const int bCol = (tid & 31) * 4;    // 0..124

    const int ty = tid >> 4;            // 0..15
    const int tx = tid & 15;            // 0..15

    float acc[TM][TN];
#pragma unroll
    for (int i = 0; i < TM; ++i)
#pragma unroll
        for (int j = 0; j < TN; ++j) acc[i][j] = 0.f;

    for (int k0 = 0; k0 < K; k0 += BK) {
#pragma unroll
        for (int p = 0; p < 2; ++p) {
            int r = aRow + p * 64;
            float4 a4 = *reinterpret_cast<const float4*>(
                &A[(size_t)(row0 + r) * K + k0 + aCol]);
            As[aCol + 0][r] = a4.x;
            As[aCol + 1][r] = a4.y;
            As[aCol + 2][r] = a4.z;
            As[aCol + 3][r] = a4.w;
        }
#pragma unroll
        for (int p = 0; p < 2; ++p) {
            int r = bRow + p * 8;
            float4 b4 = *reinterpret_cast<const float4*>(
                &B[(size_t)(k0 + r) * N + col0 + bCol]);
            *reinterpret_cast<float4*>(&Bs[r][bCol]) = b4;
        }
        __syncthreads();

#pragma unroll
        for (int kk = 0; kk < BK; ++kk) {
            float aF[TM], bF[TN];
            float4 a0 = *reinterpret_cast<const float4*>(&As[kk][ty * TM]);
            float4 a1 = *reinterpret_cast<const float4*>(&As[kk][ty * TM + 4]);
            float4 b0 = *reinterpret_cast<const float4*>(&Bs[kk][tx * TN]);
            float4 b1 = *reinterpret_cast<const float4*>(&Bs[kk][tx * TN + 4]);
            aF[0]=a0.x; aF[1]=a0.y; aF[2]=a0.z; aF[3]=a0.w;
            aF[4]=a1.x; aF[5]=a1.y; aF[6]=a1.z; aF[7]=a1.w;
            bF[0]=b0.x; bF[1]=b0.y; bF[2]=b0.z; bF[3]=b0.w;
            bF[4]=b1.x; bF[5]=b1.y; bF[6]=b1.z; bF[7]=b1.w;
#pragma unroll
            for (int i = 0; i < TM; ++i)
#pragma unroll
                for (int j = 0; j < TN; ++j)
                    acc[i][j] = fmaf(aF[i], bF[j], acc[i][j]);
        }
        __syncthreads();
    }

#pragma unroll
    for (int i = 0; i < TM; ++i) {
        int row = row0 + ty * TM + i;
#pragma unroll
        for (int j = 0; j < TN; j += 4) {
            int col = col0 + tx * TN + j;
            float4 v;
            v.x = acc[i][j + 0];
            v.y = acc[i][j + 1];
            v.z = acc[i][j + 2];
            v.w = acc[i][j + 3];
            if (WITH_BIAS) {
                v.x += bias[col + 0];
                v.y += bias[col + 1];
                v.z += bias[col + 2];
                v.w += bias[col + 3];
            }
            *reinterpret_cast<float4*>(&C[(size_t)row * N + col]) = v;
        }
    }
}

// ---------------- attention kernel ----------------
// One CTA per (window, head). 128 threads, one query row per thread.
// KV = [prev window (zeros for w==0) | current window], 256 keys, processed in
// 4 chunks of 64 with online softmax. Mask: key j (0..255) allowed iff j <= r+128,
// masked entries get -1e10 (matches reference exactly; exp underflows to 0).
#define ATTN_CHUNK 64
#define ATTN_SMEM  ((WSZ * 65 + 2 * ATTN_CHUNK * DHEAD) * sizeof(float))  // 66048 B

__global__ __launch_bounds__(WSZ, 2)
void attn_kernel(const float* __restrict__ qkv, float* __restrict__ o)
{
    extern __shared__ float sm[];
    float* qs = sm;                         // 128 x 65 (reused as per-row score buf)
    float* ks = sm + WSZ * 65;              // 64 x 64
    float* vs = ks + ATTN_CHUNK * DHEAD;    // 64 x 64

    const int w    = blockIdx.x;
    const int h    = blockIdx.y;
    const int r    = threadIdx.x;
    const int tok0 = w * WSZ;

    // load Q tile (coalesced), then pull own row into registers (pre-scaled by d^-1/2 = 0.125, exact)
    for (int i = r; i < WSZ * DHEAD; i += WSZ) {
        int row = i >> 6, col = i & 63;
        qs[row * 65 + col] = qkv[(size_t)(tok0 + row) * QKVW + h * DHEAD + col];
    }
    __syncthreads();

    float q[DHEAD];
#pragma unroll
    for (int d = 0; d < DHEAD; ++d) q[d] = qs[r * 65 + d] * 0.125f;

    float acc[DHEAD];
#pragma unroll
    for (int d = 0; d < DHEAD; ++d) acc[d] = 0.f;
    float m = -3.0e38f, l = 0.f;

    float* srow = qs + r * 65;  // row-private score buffer (safe: qs rows only read by owner after copy)

    for (int c = 0; c < 4; ++c) {
        __syncthreads();  // previous chunk fully consumed before overwriting ks/vs
        // load K,V chunk (coalesced); window 0's look-back is the zero pad
        for (int i = r; i < ATTN_CHUNK * DHEAD; i += WSZ) {
            int jj = i >> 6, col = i & 63;
            int jabs = c * ATTN_CHUNK + jj;
            float kv = 0.f, vv = 0.f;
            if (!(w == 0 && jabs < WSZ)) {
                size_t tok = (size_t)(tok0 - WSZ + jabs);
                kv = qkv[tok * QKVW +     HD + h * DHEAD + col];
                vv = qkv[tok * QKVW + 2 * HD + h * DHEAD + col];
            }
            ks[i] = kv;
            vs[i] = vv;
        }
        __syncthreads();

        // scores for this chunk -> srow (smem), dot with 4-way ILP
        for (int jj = 0; jj < ATTN_CHUNK; ++jj) {
            const float4* kr = reinterpret_cast<const float4*>(ks + jj * DHEAD);
            float s0 = 0.f, s1 = 0.f, s2 = 0.f, s3 = 0.f;
#pragma unroll
            for (int d4 = 0; d4 < DHEAD / 4; ++d4) {
                float4 kk = kr[d4];
                int d = d4 * 4;
                s0 = fmaf(q[d + 0], kk.x, s0);
                s1 = fmaf(q[d + 1], kk.y, s1);
                s2 = fmaf(q[d + 2], kk.z, s2);
                s3 = fmaf(q[d + 3], kk.w, s3);
            }
            float sv = (s0 + s1) + (s2 + s3);
            int jabs = c * ATTN_CHUNK + jj;
            srow[jj] = (jabs > r + WSZ) ? -1e10f : sv;
        }

        // chunk max (4 partials to break the dep chain)
        float m0 = -3.0e38f, m1 = -3.0e38f, m2 = -3.0e38f, m3 = -3.0e38f;
        for (int jj = 0; jj < ATTN_CHUNK; jj += 4) {
            m0 = fmaxf(m0, srow[jj + 0]);
            m1 = fmaxf(m1, srow[jj + 1]);
            m2 = fmaxf(m2, srow[jj + 2]);
            m3 = fmaxf(m3, srow[jj + 3]);
        }
        float mc = fmaxf(fmaxf(m0, m1), fmaxf(m2, m3));
        float mn = fmaxf(m, mc);
        float f  = __expf(m - mn);   // first chunk: exp(-3e38 - mn) -> 0, no NaN
        l *= f;
#pragma unroll
        for (int d = 0; d < DHEAD; ++d) acc[d] *= f;

        for (int jj = 0; jj < ATTN_CHUNK; ++jj) {
            float p = __expf(srow[jj] - mn);  // masked -> exp(~-1e10) == 0
            l += p;
            const float4* vr = reinterpret_cast<const float4*>(vs + jj * DHEAD);
#pragma unroll
            for (int d4 = 0; d4 < DHEAD / 4; ++d4) {
                float4 vv = vr[d4];
                int d = d4 * 4;
                acc[d + 0] = fmaf(p, vv.x, acc[d + 0]);
                acc[d + 1] = fmaf(p, vv.y, acc[d + 1]);
                acc[d + 2] = fmaf(p, vv.z, acc[d + 2]);
                acc[d + 3] = fmaf(p, vv.w, acc[d + 3]);
            }
        }
        m = mn;
    }

    // normalize + write: out[token, h*64+d]
    float inv = 1.0f / l;  // l > 0 always (prev window always unmasked; w==0 pad gives s=0 entries)
    float* orow = o + (size_t)(tok0 + r) * HD + h * DHEAD;
#pragma unroll
    for (int d4 = 0; d4 < DHEAD / 4; ++d4) {
        float4 vv;
        int d = d4 * 4;
        vv.x = acc[d + 0] * inv;
        vv.y = acc[d + 1] * inv;
        vv.z = acc[d + 2] * inv;
        vv.w = acc[d + 3] * inv;
        reinterpret_cast<float4*>(orow)[d4] = vv;
    }
}

// ---------------- launch ----------------
extern "C" void kernel_launch(void* const* d_in, const int* in_sizes, int n_in,
                              void* d_out, int out_size)
{
    (void)in_sizes; (void)n_in; (void)out_size;
    const float* x     = (const float*)d_in[0];  // [16384, 1024]
    const float* w_qkv = (const float*)d_in[1];  // [1024, 1536]
    const float* w_out = (const float*)d_in[2];  // [512, 1024]
    const float* b_out = (const float*)d_in[3];  // [1024]
    float*       out   = (float*)d_out;          // [16384, 1024]

    float *qkv = nullptr, *attn = nullptr;
    cudaGetSymbolAddress((void**)&qkv,  g_qkv);
    cudaGetSymbolAddress((void**)&attn, g_attn);

    // 1) QKV projection: [16384,1024] @ [1024,1536]
    {
        dim3 grid(QKVW / BN, N_TOK / BM);
        sgemm128<false><<<grid, 256>>>(x, w_qkv, nullptr, qkv, N_TOK, QKVW, DIM);
    }

    // 2) windowed look-back attention
    {
        cudaFuncSetAttribute(attn_kernel,
                             cudaFuncAttributeMaxDynamicSharedMemorySize,
                             (int)ATTN_SMEM);
        dim3 grid(NWIN, HEADS);
        attn_kernel<<<grid, WSZ, ATTN_SMEM>>>(qkv, attn);
    }

    // 3) output projection: [16384,512] @ [512,1024] + bias
    {
        dim3 grid(DIM / BN, N_TOK / BM);
        sgemm128<true><<<grid, 256>>>(attn, w_out, b_out, out, N_TOK, DIM, HD);
    }
}

// round 4
// speedup vs baseline: 2.3848x; 2.3848x over previous
#include <cuda_runtime.h>

// ---------------- problem constants ----------------
#define N_TOK   16384
#define DIM     1024
#define HEADS   8
#define DHEAD   64
#define HD      (HEADS * DHEAD)   // 512
#define QKVW    (3 * HD)          // 1536
#define WSZ     128
#define NWIN    (N_TOK / WSZ)     // 128

// ---------------- scratch (static device arrays; no allocs allowed) ----------------
__device__ float g_qkv[(size_t)N_TOK * QKVW];    // GEMM1 out (fp32)
__device__ float g_attn[(size_t)N_TOK * HD];     // attention out (tf32-rounded fp32)
__device__ float g_xc[(size_t)N_TOK * DIM];      // x rounded to tf32
__device__ float g_wqkvc[(size_t)DIM * QKVW];    // w_qkv rounded to tf32
__device__ float g_woutc[(size_t)HD * DIM];      // w_out rounded to tf32

// ---------------- helpers ----------------
__device__ __forceinline__ unsigned f2tf32(float x) {
    unsigned r;
    asm("cvt.rna.tf32.f32 %0, %1;" : "=r"(r) : "f"(x));
    return r;
}

__global__ void cvt_tf32_kernel(const float4* __restrict__ in,
                                float4* __restrict__ out, int n4)
{
    int i = blockIdx.x * blockDim.x + threadIdx.x;
    if (i < n4) {
        float4 v = in[i];
        v.x = __uint_as_float(f2tf32(v.x));
        v.y = __uint_as_float(f2tf32(v.y));
        v.z = __uint_as_float(f2tf32(v.z));
        v.w = __uint_as_float(f2tf32(v.w));
        out[i] = v;
    }
}

// ---------------- TF32 tensor-core GEMM ----------------
// C[M,N] = A[M,K] @ B[K,N] (+bias). A,B already tf32-rounded fp32, row-major.
// CTA tile 128x128x32, 8 warps (2x4), warp tile 64x32, mma.sync.m16n8k8.tf32.
// cp.async double-buffered smem; XOR swizzles keep both 16B stores and
// per-fragment LDS.32 reads bank-conflict-free.
#define GBM 128
#define GBN 128
#define GBK 32

#define CPA16(dst, src) \
    asm volatile("cp.async.cg.shared.global [%0], [%1], 16;" :: "r"(dst), "l"(src))

template <bool WITH_BIAS>
__global__ __launch_bounds__(256, 2)
void tf32gemm(const float* __restrict__ A, const float* __restrict__ B,
              const float* __restrict__ bias, float* __restrict__ C,
              int M, int N, int K)
{
    extern __shared__ float sm[];
    // floats: As stage0 [0,4096) stage1 [4096,8192); Bs stage0 [8192,12288) stage1 [12288,16384)

    const int tid  = threadIdx.x;
    const int lane = tid & 31;
    const int wm   = (tid >> 5) >> 2;   // 0..1
    const int wn   = (tid >> 5) & 3;    // 0..3
    const int g    = lane >> 2;         // groupID
    const int tg   = lane & 3;          // thread-in-group

    const int row0 = blockIdx.y * GBM;
    const int col0 = blockIdx.x * GBN;

    // loader mapping (16B granules)
    const int am = tid >> 3, ak4 = tid & 7;    // A: rows am(+32p), k4
    const int bk = tid >> 5, bn4 = tid & 31;   // B: rows bk(+8p),  n4

    unsigned smBase = (unsigned)__cvta_generic_to_shared(sm);
    // A swizzle: phys_k = k ^ (4*(m&7));  B swizzle: phys_n = n ^ (8*(k&7))
    const unsigned aDst0 = smBase + 4u * (unsigned)(am * 32 + ((4 * ak4) ^ (4 * (am & 7))));
    const unsigned bDst0 = smBase + 4u * (unsigned)(8192 + bk * 128 + 4 * (bn4 ^ (2 * (bk & 7))));
    const float* aSrc = A + (size_t)(row0 + am) * K + 4 * ak4;
    const float* bSrc = B + (size_t)bk * N + col0 + 4 * bn4;

    float acc[4][4][4];
#pragma unroll
    for (int mi = 0; mi < 4; ++mi)
#pragma unroll
        for (int ni = 0; ni < 4; ++ni)
#pragma unroll
            for (int r = 0; r < 4; ++r) acc[mi][ni][r] = 0.f;

    const int nk = K / GBK;

    auto issue = [&](int kt, int s) {
        const float* ap = aSrc + kt * GBK;
        unsigned ad = aDst0 + (unsigned)s * 16384u;
#pragma unroll
        for (int p = 0; p < 4; ++p)
            CPA16(ad + (unsigned)p * 4096u, ap + (size_t)p * 32 * K);
        const float* bp = bSrc + (size_t)kt * GBK * N;
        unsigned bd = bDst0 + (unsigned)s * 16384u;
#pragma unroll
        for (int p = 0; p < 4; ++p)
            CPA16(bd + (unsigned)p * 4096u, bp + (size_t)p * 8 * N);
        asm volatile("cp.async.commit_group;");
    };

    issue(0, 0);

    for (int kt = 0; kt < nk; ++kt) {
        const int s = kt & 1;
        if (kt + 1 < nk) {
            issue(kt + 1, s ^ 1);
            asm volatile("cp.async.wait_group 1;");
        } else {
            asm volatile("cp.async.wait_group 0;");
        }
        __syncthreads();

        const unsigned* as = reinterpret_cast<const unsigned*>(sm + s * 4096);
        const unsigned* bs = reinterpret_cast<const unsigned*>(sm + 8192 + s * 4096);

#pragma unroll
        for (int ks = 0; ks < 4; ++ks) {
            unsigned a[4][4];
#pragma unroll
            for (int mi = 0; mi < 4; ++mi) {
                int m0 = wm * 64 + mi * 16 + g;
                int sw = 4 * (m0 & 7);
                int k0 = 8 * ks + tg;
                a[mi][0] = as[m0 * 32 + (k0 ^ sw)];
                a[mi][1] = as[(m0 + 8) * 32 + (k0 ^ sw)];
                a[mi][2] = as[m0 * 32 + ((k0 + 4) ^ sw)];
                a[mi][3] = as[(m0 + 8) * 32 + ((k0 + 4) ^ sw)];
            }
            unsigned b[4][2];
#pragma unroll
            for (int ni = 0; ni < 4; ++ni) {
                int n0 = wn * 32 + ni * 8 + g;
                int k0 = 8 * ks + tg;
                int k1 = k0 + 4;
                b[ni][0] = bs[k0 * 128 + (n0 ^ (8 * (k0 & 7)))];
                b[ni][1] = bs[k1 * 128 + (n0 ^ (8 * (k1 & 7)))];
            }
#pragma unroll
            for (int mi = 0; mi < 4; ++mi)
#pragma unroll
                for (int ni = 0; ni < 4; ++ni)
                    asm volatile(
                        "mma.sync.aligned.m16n8k8.row.col.f32.tf32.tf32.f32 "
                        "{%0,%1,%2,%3}, {%4,%5,%6,%7}, {%8,%9}, {%0,%1,%2,%3};"
                        : "+f"(acc[mi][ni][0]), "+f"(acc[mi][ni][1]),
                          "+f"(acc[mi][ni][2]), "+f"(acc[mi][ni][3])
                        : "r"(a[mi][0]), "r"(a[mi][1]), "r"(a[mi][2]), "r"(a[mi][3]),
                          "r"(b[ni][0]), "r"(b[ni][1]));
        }
        __syncthreads();
    }

    // epilogue: c0/c1 -> (row, 2tg), c2/c3 -> (row+8, 2tg)
#pragma unroll
    for (int ni = 0; ni < 4; ++ni) {
        int col = col0 + wn * 32 + ni * 8 + 2 * tg;
        float bx = 0.f, by = 0.f;
        if (WITH_BIAS) { bx = bias[col]; by = bias[col + 1]; }
#pragma unroll
        for (int mi = 0; mi < 4; ++mi) {
            int row = row0 + wm * 64 + mi * 16 + g;
            float2 v0 = make_float2(acc[mi][ni][0] + bx, acc[mi][ni][1] + by);
            float2 v1 = make_float2(acc[mi][ni][2] + bx, acc[mi][ni][3] + by);
            *reinterpret_cast<float2*>(&C[(size_t)row * N + col]) = v0;
            *reinterpret_cast<float2*>(&C[(size_t)(row + 8) * N + col]) = v1;
        }
    }
}

// ---------------- attention kernel (unchanged math; tf32-rounded output) ----------------
#define ATTN_CHUNK 64
#define ATTN_SMEM  ((WSZ * 65 + 2 * ATTN_CHUNK * DHEAD) * sizeof(float))  // 66048 B

__global__ __launch_bounds__(WSZ, 2)
void attn_kernel(const float* __restrict__ qkv, float* __restrict__ o)
{
    extern __shared__ float smA[];
    float* qs = smA;                        // 128 x 65 (reused as per-row score buf)
    float* ks = smA + WSZ * 65;             // 64 x 64
    float* vs = ks + ATTN_CHUNK * DHEAD;    // 64 x 64

    const int w    = blockIdx.x;
    const int h    = blockIdx.y;
    const int r    = threadIdx.x;
    const int tok0 = w * WSZ;

    for (int i = r; i < WSZ * DHEAD; i += WSZ) {
        int row = i >> 6, col = i & 63;
        qs[row * 65 + col] = qkv[(size_t)(tok0 + row) * QKVW + h * DHEAD + col];
    }
    __syncthreads();

    float q[DHEAD];
#pragma unroll
    for (int d = 0; d < DHEAD; ++d) q[d] = qs[r * 65 + d] * 0.125f;

    float acc[DHEAD];
#pragma unroll
    for (int d = 0; d < DHEAD; ++d) acc[d] = 0.f;
    float m = -3.0e38f, l = 0.f;

    float* srow = qs + r * 65;

    for (int c = 0; c < 4; ++c) {
        __syncthreads();
        for (int i = r; i < ATTN_CHUNK * DHEAD; i += WSZ) {
            int jj = i >> 6, col = i & 63;
            int jabs = c * ATTN_CHUNK + jj;
            float kv = 0.f, vv = 0.f;
            if (!(w == 0 && jabs < WSZ)) {
                size_t tok = (size_t)(tok0 - WSZ + jabs);
                kv = qkv[tok * QKVW +     HD + h * DHEAD + col];
                vv = qkv[tok * QKVW + 2 * HD + h * DHEAD + col];
            }
            ks[i] = kv;
            vs[i] = vv;
        }
        __syncthreads();

        for (int jj = 0; jj < ATTN_CHUNK; ++jj) {
            const float4* kr = reinterpret_cast<const float4*>(ks + jj * DHEAD);
            float s0 = 0.f, s1 = 0.f, s2 = 0.f, s3 = 0.f;
#pragma unroll
            for (int d4 = 0; d4 < DHEAD / 4; ++d4) {
                float4 kk = kr[d4];
                int d = d4 * 4;
                s0 = fmaf(q[d + 0], kk.x, s0);
                s1 = fmaf(q[d + 1], kk.y, s1);
                s2 = fmaf(q[d + 2], kk.z, s2);
                s3 = fmaf(q[d + 3], kk.w, s3);
            }
            float sv = (s0 + s1) + (s2 + s3);
            int jabs = c * ATTN_CHUNK + jj;
            srow[jj] = (jabs > r + WSZ) ? -1e10f : sv;
        }

        float m0 = -3.0e38f, m1 = -3.0e38f, m2 = -3.0e38f, m3 = -3.0e38f;
        for (int jj = 0; jj < ATTN_CHUNK; jj += 4) {
            m0 = fmaxf(m0, srow[jj + 0]);
            m1 = fmaxf(m1, srow[jj + 1]);
            m2 = fmaxf(m2, srow[jj + 2]);
            m3 = fmaxf(m3, srow[jj + 3]);
        }
        float mc = fmaxf(fmaxf(m0, m1), fmaxf(m2, m3));
        float mn = fmaxf(m, mc);
        float f  = __expf(m - mn);
        l *= f;
#pragma unroll
        for (int d = 0; d < DHEAD; ++d) acc[d] *= f;

        for (int jj = 0; jj < ATTN_CHUNK; ++jj) {
            float p = __expf(srow[jj] - mn);
            l += p;
            const float4* vr = reinterpret_cast<const float4*>(vs + jj * DHEAD);
#pragma unroll
            for (int d4 = 0; d4 < DHEAD / 4; ++d4) {
                float4 vv = vr[d4];
                int d = d4 * 4;
                acc[d + 0] = fmaf(p, vv.x, acc[d + 0]);
                acc[d + 1] = fmaf(p, vv.y, acc[d + 1]);
                acc[d + 2] = fmaf(p, vv.z, acc[d + 2]);
                acc[d + 3] = fmaf(p, vv.w, acc[d + 3]);
            }
        }
        m = mn;
    }

    float inv = 1.0f / l;
    float* orow = o + (size_t)(tok0 + r) * HD + h * DHEAD;
#pragma unroll
    for (int d4 = 0; d4 < DHEAD / 4; ++d4) {
        float4 vv;
        int d = d4 * 4;
        vv.x = __uint_as_float(f2tf32(acc[d + 0] * inv));
        vv.y = __uint_as_float(f2tf32(acc[d + 1] * inv));
        vv.z = __uint_as_float(f2tf32(acc[d + 2] * inv));
        vv.w = __uint_as_float(f2tf32(acc[d + 3] * inv));
        reinterpret_cast<float4*>(orow)[d4] = vv;
    }
}

// ---------------- launch ----------------
extern "C" void kernel_launch(void* const* d_in, const int* in_sizes, int n_in,
                              void* d_out, int out_size)
{
    (void)in_sizes; (void)n_in; (void)out_size;
    const float* x     = (const float*)d_in[0];  // [16384, 1024]
    const float* w_qkv = (const float*)d_in[1];  // [1024, 1536]
    const float* w_out = (const float*)d_in[2];  // [512, 1024]
    const float* b_out = (const float*)d_in[3];  // [1024]
    float*       out   = (float*)d_out;          // [16384, 1024]

    float *qkv = nullptr, *attn = nullptr, *xc = nullptr, *wqkvc = nullptr, *woutc = nullptr;
    cudaGetSymbolAddress((void**)&qkv,   g_qkv);
    cudaGetSymbolAddress((void**)&attn,  g_attn);
    cudaGetSymbolAddress((void**)&xc,    g_xc);
    cudaGetSymbolAddress((void**)&wqkvc, g_wqkvc);
    cudaGetSymbolAddress((void**)&woutc, g_woutc);

    const int GEMM_SMEM = 16384 * (int)sizeof(float);  // 64 KB
    cudaFuncSetAttribute(tf32gemm<false>, cudaFuncAttributeMaxDynamicSharedMemorySize, GEMM_SMEM);
    cudaFuncSetAttribute(tf32gemm<true>,  cudaFuncAttributeMaxDynamicSharedMemorySize, GEMM_SMEM);

    // 0) round inputs to tf32 (RN) so GEMM hot loops need no cvt and no truncation bias
    {
        int n4;
        n4 = N_TOK * DIM / 4;
        cvt_tf32_kernel<<<(n4 + 255) / 256, 256>>>((const float4*)x, (float4*)xc, n4);
        n4 = DIM * QKVW / 4;
        cvt_tf32_kernel<<<(n4 + 255) / 256, 256>>>((const float4*)w_qkv, (float4*)wqkvc, n4);
        n4 = HD * DIM / 4;
        cvt_tf32_kernel<<<(n4 + 255) / 256, 256>>>((const float4*)w_out, (float4*)woutc, n4);
    }

    // 1) QKV projection: [16384,1024] @ [1024,1536]  (tf32 tensor cores)
    {
        dim3 grid(QKVW / GBN, N_TOK / GBM);
        tf32gemm<false><<<grid, 256, GEMM_SMEM>>>(xc, wqkvc, nullptr, qkv, N_TOK, QKVW, DIM);
    }

    // 2) windowed look-back attention (fp32)
    {
        cudaFuncSetAttribute(attn_kernel,
                             cudaFuncAttributeMaxDynamicSharedMemorySize, (int)ATTN_SMEM);
        dim3 grid(NWIN, HEADS);
        attn_kernel<<<grid, WSZ, ATTN_SMEM>>>(qkv, attn);
    }

    // 3) output projection: [16384,512] @ [512,1024] + bias  (tf32 tensor cores)
    {
        dim3 grid(DIM / GBN, N_TOK / GBM);
        tf32gemm<true><<<grid, 256, GEMM_SMEM>>>(attn, woutc, b_out, out, N_TOK, DIM, HD);
    }
}

// round 5
// speedup vs baseline: 3.4276x; 1.4373x over previous
#include <cuda_runtime.h>

// ---------------- problem constants ----------------
#define N_TOK   16384
#define DIM     1024
#define HEADS   8
#define DHEAD   64
#define HD      (HEADS * DHEAD)   // 512
#define QKVW    (3 * HD)          // 1536
#define WSZ     128
#define NWIN    (N_TOK / WSZ)     // 128

// ---------------- scratch (static device arrays; no allocs allowed) ----------------
__device__ float g_qkv[(size_t)N_TOK * QKVW];    // GEMM1 out (fp32)
__device__ float g_attn[(size_t)N_TOK * HD];     // attention out (tf32-rounded fp32)
__device__ float g_xc[(size_t)N_TOK * DIM];      // x rounded to tf32
__device__ float g_wqkvc[(size_t)DIM * QKVW];    // w_qkv rounded to tf32
__device__ float g_woutc[(size_t)HD * DIM];      // w_out rounded to tf32

// ---------------- helpers ----------------
__device__ __forceinline__ unsigned f2tf32(float x) {
    unsigned r;
    asm("cvt.rna.tf32.f32 %0, %1;" : "=r"(r) : "f"(x));
    return r;
}

__device__ __forceinline__ void mma_tf32(float c[4], const unsigned a[4],
                                         unsigned b0, unsigned b1) {
    asm volatile(
        "mma.sync.aligned.m16n8k8.row.col.f32.tf32.tf32.f32 "
        "{%0,%1,%2,%3}, {%4,%5,%6,%7}, {%8,%9}, {%0,%1,%2,%3};"
        : "+f"(c[0]), "+f"(c[1]), "+f"(c[2]), "+f"(c[3])
        : "r"(a[0]), "r"(a[1]), "r"(a[2]), "r"(a[3]), "r"(b0), "r"(b1));
}

__global__ void cvt_tf32_kernel(const float4* __restrict__ in,
                                float4* __restrict__ out, int n4)
{
    int i = blockIdx.x * blockDim.x + threadIdx.x;
    if (i < n4) {
        float4 v = in[i];
        v.x = __uint_as_float(f2tf32(v.x));
        v.y = __uint_as_float(f2tf32(v.y));
        v.z = __uint_as_float(f2tf32(v.z));
        v.w = __uint_as_float(f2tf32(v.w));
        out[i] = v;
    }
}

// ---------------- TF32 tensor-core GEMM (unchanged from round 3) ----------------
#define GBM 128
#define GBN 128
#define GBK 32

#define CPA16(dst, src) \
    asm volatile("cp.async.cg.shared.global [%0], [%1], 16;" :: "r"(dst), "l"(src))

template <bool WITH_BIAS>
__global__ __launch_bounds__(256, 2)
void tf32gemm(const float* __restrict__ A, const float* __restrict__ B,
              const float* __restrict__ bias, float* __restrict__ C,
              int M, int N, int K)
{
    extern __shared__ float sm[];

    const int tid  = threadIdx.x;
    const int lane = tid & 31;
    const int wm   = (tid >> 5) >> 2;   // 0..1
    const int wn   = (tid >> 5) & 3;    // 0..3
    const int g    = lane >> 2;
    const int tg   = lane & 3;

    const int row0 = blockIdx.y * GBM;
    const int col0 = blockIdx.x * GBN;

    const int am = tid >> 3, ak4 = tid & 7;
    const int bk = tid >> 5, bn4 = tid & 31;

    unsigned smBase = (unsigned)__cvta_generic_to_shared(sm);
    const unsigned aDst0 = smBase + 4u * (unsigned)(am * 32 + ((4 * ak4) ^ (4 * (am & 7))));
    const unsigned bDst0 = smBase + 4u * (unsigned)(8192 + bk * 128 + 4 * (bn4 ^ (2 * (bk & 7))));
    const float* aSrc = A + (size_t)(row0 + am) * K + 4 * ak4;
    const float* bSrc = B + (size_t)bk * N + col0 + 4 * bn4;

    float acc[4][4][4];
#pragma unroll
    for (int mi = 0; mi < 4; ++mi)
#pragma unroll
        for (int ni = 0; ni < 4; ++ni)
#pragma unroll
            for (int r = 0; r < 4; ++r) acc[mi][ni][r] = 0.f;

    const int nk = K / GBK;

    auto issue = [&](int kt, int s) {
        const float* ap = aSrc + kt * GBK;
        unsigned ad = aDst0 + (unsigned)s * 16384u;
#pragma unroll
        for (int p = 0; p < 4; ++p)
            CPA16(ad + (unsigned)p * 4096u, ap + (size_t)p * 32 * K);
        const float* bp = bSrc + (size_t)kt * GBK * N;
        unsigned bd = bDst0 + (unsigned)s * 16384u;
#pragma unroll
        for (int p = 0; p < 4; ++p)
            CPA16(bd + (unsigned)p * 4096u, bp + (size_t)p * 8 * N);
        asm volatile("cp.async.commit_group;");
    };

    issue(0, 0);

    for (int kt = 0; kt < nk; ++kt) {
        const int s = kt & 1;
        if (kt + 1 < nk) {
            issue(kt + 1, s ^ 1);
            asm volatile("cp.async.wait_group 1;");
        } else {
            asm volatile("cp.async.wait_group 0;");
        }
        __syncthreads();

        const unsigned* as = reinterpret_cast<const unsigned*>(sm + s * 4096);
        const unsigned* bs = reinterpret_cast<const unsigned*>(sm + 8192 + s * 4096);

#pragma unroll
        for (int ks = 0; ks < 4; ++ks) {
            unsigned a[4][4];
#pragma unroll
            for (int mi = 0; mi < 4; ++mi) {
                int m0 = wm * 64 + mi * 16 + g;
                int sw = 4 * (m0 & 7);
                int k0 = 8 * ks + tg;
                a[mi][0] = as[m0 * 32 + (k0 ^ sw)];
                a[mi][1] = as[(m0 + 8) * 32 + (k0 ^ sw)];
                a[mi][2] = as[m0 * 32 + ((k0 + 4) ^ sw)];
                a[mi][3] = as[(m0 + 8) * 32 + ((k0 + 4) ^ sw)];
            }
            unsigned b[4][2];
#pragma unroll
            for (int ni = 0; ni < 4; ++ni) {
                int n0 = wn * 32 + ni * 8 + g;
                int k0 = 8 * ks + tg;
                int k1 = k0 + 4;
                b[ni][0] = bs[k0 * 128 + (n0 ^ (8 * (k0 & 7)))];
                b[ni][1] = bs[k1 * 128 + (n0 ^ (8 * (k1 & 7)))];
            }
#pragma unroll
            for (int mi = 0; mi < 4; ++mi)
#pragma unroll
                for (int ni = 0; ni < 4; ++ni)
                    mma_tf32(acc[mi][ni], a[mi], b[ni][0], b[ni][1]);
        }
        __syncthreads();
    }

#pragma unroll
    for (int ni = 0; ni < 4; ++ni) {
        int col = col0 + wn * 32 + ni * 8 + 2 * tg;
        float bx = 0.f, by = 0.f;
        if (WITH_BIAS) { bx = bias[col]; by = bias[col + 1]; }
#pragma unroll
        for (int mi = 0; mi < 4; ++mi) {
            int row = row0 + wm * 64 + mi * 16 + g;
            float2 v0 = make_float2(acc[mi][ni][0] + bx, acc[mi][ni][1] + by);
            float2 v1 = make_float2(acc[mi][ni][2] + bx, acc[mi][ni][3] + by);
            *reinterpret_cast<float2*>(&C[(size_t)row * N + col]) = v0;
            *reinterpret_cast<float2*>(&C[(size_t)(row + 8) * N + col]) = v1;
        }
    }
}

// ---------------- tensor-core attention ----------------
// One CTA per (window, head). 8 warps x 16 query rows. S = Q@K^T via
// m16n8k8 tf32 mma (K smem [256][68], conflict-free), register softmax
// (quad shfl reductions), P@V via mma with P re-fragmented by shuffles
// (V smem [256][72], conflict-free).
#define KS_STRIDE 68
#define VS_STRIDE 72
#define ATTN_SMEM ((256 * KS_STRIDE + 256 * VS_STRIDE) * sizeof(float))  // 143360

__global__ __launch_bounds__(256, 1)
void attn_mma_kernel(const float* __restrict__ qkv, float* __restrict__ o)
{
    extern __shared__ float smA[];
    float* ks = smA;                      // [256][68] (Q staging first, then K)
    float* vs = smA + 256 * KS_STRIDE;    // [256][72]

    const int w    = blockIdx.x;
    const int h    = blockIdx.y;
    const int tid  = threadIdx.x;
    const int lane = tid & 31;
    const int wq   = tid >> 5;            // 0..7
    const int g    = lane >> 2;           // 0..7
    const int tg   = lane & 3;            // 0..3
    const int m0   = wq * 16;
    const int tok0 = w * WSZ;

    // ---- stage Q (scaled by d^-1/2 = 0.125, tf32-rounded) into ks area ----
    for (int i = tid; i < WSZ * 16; i += 256) {          // float4 granules
        int row = i >> 4, c4 = (i & 15) * 4;
        float4 v = *reinterpret_cast<const float4*>(
            &qkv[(size_t)(tok0 + row) * QKVW + h * DHEAD + c4]);
        float4 r;
        r.x = __uint_as_float(f2tf32(v.x * 0.125f));
        r.y = __uint_as_float(f2tf32(v.y * 0.125f));
        r.z = __uint_as_float(f2tf32(v.z * 0.125f));
        r.w = __uint_as_float(f2tf32(v.w * 0.125f));
        *reinterpret_cast<float4*>(&ks[row * KS_STRIDE + c4]) = r;
    }
    __syncthreads();

    // per-warp Q A-fragments (8 k-steps x 4 regs); bank pattern 4g+tg: conflict-free
    unsigned qa[8][4];
#pragma unroll
    for (int kt = 0; kt < 8; ++kt) {
        int k0 = 8 * kt + tg;
        qa[kt][0] = __float_as_uint(ks[(m0 + g) * KS_STRIDE + k0]);
        qa[kt][1] = __float_as_uint(ks[(m0 + g + 8) * KS_STRIDE + k0]);
        qa[kt][2] = __float_as_uint(ks[(m0 + g) * KS_STRIDE + k0 + 4]);
        qa[kt][3] = __float_as_uint(ks[(m0 + g + 8) * KS_STRIDE + k0 + 4]);
    }
    __syncthreads();

    // ---- load K, V (256 keys = prev window | current; prev is zero for w==0) ----
    for (int i = tid; i < 256 * 16; i += 256) {
        int j = i >> 4, c4 = (i & 15) * 4;
        float4 kv = make_float4(0.f, 0.f, 0.f, 0.f);
        float4 vv = make_float4(0.f, 0.f, 0.f, 0.f);
        if (!(w == 0 && j < WSZ)) {
            size_t tok = (size_t)(tok0 - WSZ + j);
            kv = *reinterpret_cast<const float4*>(&qkv[tok * QKVW +     HD + h * DHEAD + c4]);
            vv = *reinterpret_cast<const float4*>(&qkv[tok * QKVW + 2 * HD + h * DHEAD + c4]);
        }
        float4 kr, vr;
        kr.x = __uint_as_float(f2tf32(kv.x)); kr.y = __uint_as_float(f2tf32(kv.y));
        kr.z = __uint_as_float(f2tf32(kv.z)); kr.w = __uint_as_float(f2tf32(kv.w));
        vr.x = __uint_as_float(f2tf32(vv.x)); vr.y = __uint_as_float(f2tf32(vv.y));
        vr.z = __uint_as_float(f2tf32(vv.z)); vr.w = __uint_as_float(f2tf32(vv.w));
        *reinterpret_cast<float4*>(&ks[j * KS_STRIDE + c4]) = kr;
        *reinterpret_cast<float4*>(&vs[j * VS_STRIDE + c4]) = vr;
    }
    __syncthreads();

    // ---- S = Q @ K^T : 32 n-tiles x 8 k-steps of m16n8k8 ----
    float s[32][4];
#pragma unroll
    for (int nt = 0; nt < 32; ++nt) {
        s[nt][0] = 0.f; s[nt][1] = 0.f; s[nt][2] = 0.f; s[nt][3] = 0.f;
        const int n0 = 8 * nt + g;
#pragma unroll
        for (int kt = 0; kt < 8; ++kt) {
            int k0 = 8 * kt + tg;
            unsigned b0 = __float_as_uint(ks[n0 * KS_STRIDE + k0]);
            unsigned b1 = __float_as_uint(ks[n0 * KS_STRIDE + k0 + 4]);
            mma_tf32(s[nt], qa[kt], b0, b1);
        }
    }

    // ---- mask + softmax (rows i_lo = m0+g, i_hi = i_lo+8; allowed j <= i+128) ----
    const int i_lo = m0 + g, i_hi = i_lo + 8;
    float mx0 = -3.0e38f, mx1 = -3.0e38f;
#pragma unroll
    for (int nt = 0; nt < 32; ++nt) {
        int j0 = 8 * nt + 2 * tg, j1 = j0 + 1;
        if (j0 > i_lo + WSZ) s[nt][0] = -1e10f;
        if (j1 > i_lo + WSZ) s[nt][1] = -1e10f;
        if (j0 > i_hi + WSZ) s[nt][2] = -1e10f;
        if (j1 > i_hi + WSZ) s[nt][3] = -1e10f;
        mx0 = fmaxf(mx0, fmaxf(s[nt][0], s[nt][1]));
        mx1 = fmaxf(mx1, fmaxf(s[nt][2], s[nt][3]));
    }
    mx0 = fmaxf(mx0, __shfl_xor_sync(0xffffffffu, mx0, 1));
    mx0 = fmaxf(mx0, __shfl_xor_sync(0xffffffffu, mx0, 2));
    mx1 = fmaxf(mx1, __shfl_xor_sync(0xffffffffu, mx1, 1));
    mx1 = fmaxf(mx1, __shfl_xor_sync(0xffffffffu, mx1, 2));

    float l0 = 0.f, l1 = 0.f;
#pragma unroll
    for (int nt = 0; nt < 32; ++nt) {
        float p0 = __expf(s[nt][0] - mx0);
        float p1 = __expf(s[nt][1] - mx0);
        float p2 = __expf(s[nt][2] - mx1);
        float p3 = __expf(s[nt][3] - mx1);
        l0 += p0 + p1;
        l1 += p2 + p3;
        s[nt][0] = __uint_as_float(f2tf32(p0));
        s[nt][1] = __uint_as_float(f2tf32(p1));
        s[nt][2] = __uint_as_float(f2tf32(p2));
        s[nt][3] = __uint_as_float(f2tf32(p3));
    }
    l0 += __shfl_xor_sync(0xffffffffu, l0, 1);
    l0 += __shfl_xor_sync(0xffffffffu, l0, 2);
    l1 += __shfl_xor_sync(0xffffffffu, l1, 1);
    l1 += __shfl_xor_sync(0xffffffffu, l1, 2);

    // ---- O = P @ V : 32 k-steps, 8 n-tiles; P re-fragmented via shuffles ----
    float ov[8][4];
#pragma unroll
    for (int nt = 0; nt < 8; ++nt) {
        ov[nt][0] = 0.f; ov[nt][1] = 0.f; ov[nt][2] = 0.f; ov[nt][3] = 0.f;
    }

#pragma unroll
    for (int kj = 0; kj < 32; ++kj) {
        // A fragment: a0=P(g, 8kj+tg) a1=P(g+8, 8kj+tg) a2=P(g, 8kj+tg+4) a3=P(g+8, 8kj+tg+4)
        int src0 = (lane & ~3) | (tg >> 1);
        int src2 = src0 + 2;
        float v00 = __shfl_sync(0xffffffffu, s[kj][0], src0);
        float v01 = __shfl_sync(0xffffffffu, s[kj][1], src0);
        float v10 = __shfl_sync(0xffffffffu, s[kj][2], src0);
        float v11 = __shfl_sync(0xffffffffu, s[kj][3], src0);
        float v20 = __shfl_sync(0xffffffffu, s[kj][0], src2);
        float v21 = __shfl_sync(0xffffffffu, s[kj][1], src2);
        float v30 = __shfl_sync(0xffffffffu, s[kj][2], src2);
        float v31 = __shfl_sync(0xffffffffu, s[kj][3], src2);
        bool odd = (tg & 1);
        unsigned a[4];
        a[0] = __float_as_uint(odd ? v01 : v00);
        a[1] = __float_as_uint(odd ? v11 : v10);
        a[2] = __float_as_uint(odd ? v21 : v20);
        a[3] = __float_as_uint(odd ? v31 : v30);

        const int j0 = 8 * kj + tg;
#pragma unroll
        for (int nt = 0; nt < 8; ++nt) {
            unsigned b0 = __float_as_uint(vs[j0 * VS_STRIDE + 8 * nt + g]);
            unsigned b1 = __float_as_uint(vs[(j0 + 4) * VS_STRIDE + 8 * nt + g]);
            mma_tf32(ov[nt], a, b0, b1);
        }
    }

    // ---- normalize + write (tf32-rounded so GEMM2 needs no cvt) ----
    float inv0 = 1.f / l0, inv1 = 1.f / l1;
    const int row_lo = tok0 + m0 + g;
#pragma unroll
    for (int nt = 0; nt < 8; ++nt) {
        int col = h * DHEAD + 8 * nt + 2 * tg;
        float2 w0, w1;
        w0.x = __uint_as_float(f2tf32(ov[nt][0] * inv0));
        w0.y = __uint_as_float(f2tf32(ov[nt][1] * inv0));
        w1.x = __uint_as_float(f2tf32(ov[nt][2] * inv1));
        w1.y = __uint_as_float(f2tf32(ov[nt][3] * inv1));
        *reinterpret_cast<float2*>(&o[(size_t)row_lo * HD + col]) = w0;
        *reinterpret_cast<float2*>(&o[(size_t)(row_lo + 8) * HD + col]) = w1;
    }
}

// ---------------- launch ----------------
extern "C" void kernel_launch(void* const* d_in, const int* in_sizes, int n_in,
                              void* d_out, int out_size)
{
    (void)in_sizes; (void)n_in; (void)out_size;
    const float* x     = (const float*)d_in[0];  // [16384, 1024]
    const float* w_qkv = (const float*)d_in[1];  // [1024, 1536]
    const float* w_out = (const float*)d_in[2];  // [512, 1024]
    const float* b_out = (const float*)d_in[3];  // [1024]
    float*       out   = (float*)d_out;          // [16384, 1024]

    float *qkv = nullptr, *attn = nullptr, *xc = nullptr, *wqkvc = nullptr, *woutc = nullptr;
    cudaGetSymbolAddress((void**)&qkv,   g_qkv);
    cudaGetSymbolAddress((void**)&attn,  g_attn);
    cudaGetSymbolAddress((void**)&xc,    g_xc);
    cudaGetSymbolAddress((void**)&wqkvc, g_wqkvc);
    cudaGetSymbolAddress((void**)&woutc, g_woutc);

    const int GEMM_SMEM = 16384 * (int)sizeof(float);  // 64 KB
    cudaFuncSetAttribute(tf32gemm<false>, cudaFuncAttributeMaxDynamicSharedMemorySize, GEMM_SMEM);
    cudaFuncSetAttribute(tf32gemm<true>,  cudaFuncAttributeMaxDynamicSharedMemorySize, GEMM_SMEM);
    cudaFuncSetAttribute(attn_mma_kernel, cudaFuncAttributeMaxDynamicSharedMemorySize, (int)ATTN_SMEM);

    // 0) round inputs to tf32 (RN)
    {
        int n4;
        n4 = N_TOK * DIM / 4;
        cvt_tf32_kernel<<<(n4 + 255) / 256, 256>>>((const float4*)x, (float4*)xc, n4);
        n4 = DIM * QKVW / 4;
        cvt_tf32_kernel<<<(n4 + 255) / 256, 256>>>((const float4*)w_qkv, (float4*)wqkvc, n4);
        n4 = HD * DIM / 4;
        cvt_tf32_kernel<<<(n4 + 255) / 256, 256>>>((const float4*)w_out, (float4*)woutc, n4);
    }

    // 1) QKV projection: [16384,1024] @ [1024,1536]  (tf32 tensor cores)
    {
        dim3 grid(QKVW / GBN, N_TOK / GBM);
        tf32gemm<false><<<grid, 256, GEMM_SMEM>>>(xc, wqkvc, nullptr, qkv, N_TOK, QKVW, DIM);
    }

    // 2) windowed look-back attention (tf32 tensor cores)
    {
        dim3 grid(NWIN, HEADS);
        attn_mma_kernel<<<grid, 256, ATTN_SMEM>>>(qkv, attn);
    }

    // 3) output projection: [16384,512] @ [512,1024] + bias  (tf32 tensor cores)
    {
        dim3 grid(DIM / GBN, N_TOK / GBM);
        tf32gemm<true><<<grid, 256, GEMM_SMEM>>>(attn, woutc, b_out, out, N_TOK, DIM, HD);
    }
}